// round 16
// baseline (speedup 1.0000x reference)
#include <cuda_runtime.h>
#include <math.h>

#define H 64
#define MAX_N 65536
#define CAP 64
#define MAX_OVF 65536

// Fused counter block: [0, MAX_N) = in-degree bin cursors (cnt),
// [MAX_N, 2*MAX_N) = out-degree, [2*MAX_N] = overflow counter (padded to 4).
#define META_INTS (2 * MAX_N + 4)
__device__ int   g_meta[META_INTS];
__device__ float g_srcnorm[MAX_N];      // rsqrt(max(degout,1))
__device__ int   g_ebuf[MAX_N * CAP];   // dst-binned src indices
__device__ int2  g_ovf[MAX_OVF];        // overflow (dst, src) pairs

#define g_cnt    (g_meta)
#define g_degout (g_meta + MAX_N)
#define g_ovfn   (g_meta + 2 * MAX_N)

// Zero + L2-warm all counters. int4 stores, one pass.
__global__ void k_zero() {
    int i = blockIdx.x * blockDim.x + threadIdx.x;
    if (i < META_INTS / 4)
        ((int4*)g_meta)[i] = make_int4(0, 0, 0, 0);
}

// One pass over edges: out-degree histogram + dst-binning. 8 edges/thread
// (2x int4 loads, 16 independent atomics in flight).
__global__ void k_bin(const int* __restrict__ src, const int* __restrict__ dst, int e) {
    int t = blockIdx.x * blockDim.x + threadIdx.x;
    int i = t * 8;
    if (i + 7 < e) {
        int4 sa = *(const int4*)(src + i);
        int4 sb = *(const int4*)(src + i + 4);
        int4 da = *(const int4*)(dst + i);
        int4 db = *(const int4*)(dst + i + 4);
        atomicAdd(&g_degout[sa.x], 1); atomicAdd(&g_degout[sa.y], 1);
        atomicAdd(&g_degout[sa.z], 1); atomicAdd(&g_degout[sa.w], 1);
        atomicAdd(&g_degout[sb.x], 1); atomicAdd(&g_degout[sb.y], 1);
        atomicAdd(&g_degout[sb.z], 1); atomicAdd(&g_degout[sb.w], 1);
        int p0 = atomicAdd(&g_cnt[da.x], 1);
        int p1 = atomicAdd(&g_cnt[da.y], 1);
        int p2 = atomicAdd(&g_cnt[da.z], 1);
        int p3 = atomicAdd(&g_cnt[da.w], 1);
        int p4 = atomicAdd(&g_cnt[db.x], 1);
        int p5 = atomicAdd(&g_cnt[db.y], 1);
        int p6 = atomicAdd(&g_cnt[db.z], 1);
        int p7 = atomicAdd(&g_cnt[db.w], 1);
        if (p0 < CAP) g_ebuf[da.x * CAP + p0] = sa.x;
        else { int k = atomicAdd(g_ovfn, 1); if (k < MAX_OVF) g_ovf[k] = make_int2(da.x, sa.x); }
        if (p1 < CAP) g_ebuf[da.y * CAP + p1] = sa.y;
        else { int k = atomicAdd(g_ovfn, 1); if (k < MAX_OVF) g_ovf[k] = make_int2(da.y, sa.y); }
        if (p2 < CAP) g_ebuf[da.z * CAP + p2] = sa.z;
        else { int k = atomicAdd(g_ovfn, 1); if (k < MAX_OVF) g_ovf[k] = make_int2(da.z, sa.z); }
        if (p3 < CAP) g_ebuf[da.w * CAP + p3] = sa.w;
        else { int k = atomicAdd(g_ovfn, 1); if (k < MAX_OVF) g_ovf[k] = make_int2(da.w, sa.w); }
        if (p4 < CAP) g_ebuf[db.x * CAP + p4] = sb.x;
        else { int k = atomicAdd(g_ovfn, 1); if (k < MAX_OVF) g_ovf[k] = make_int2(db.x, sb.x); }
        if (p5 < CAP) g_ebuf[db.y * CAP + p5] = sb.y;
        else { int k = atomicAdd(g_ovfn, 1); if (k < MAX_OVF) g_ovf[k] = make_int2(db.y, sb.y); }
        if (p6 < CAP) g_ebuf[db.z * CAP + p6] = sb.z;
        else { int k = atomicAdd(g_ovfn, 1); if (k < MAX_OVF) g_ovf[k] = make_int2(db.z, sb.z); }
        if (p7 < CAP) g_ebuf[db.w * CAP + p7] = sb.w;
        else { int k = atomicAdd(g_ovfn, 1); if (k < MAX_OVF) g_ovf[k] = make_int2(db.w, sb.w); }
    } else {
        for (; i < e && i < t * 8 + 8; ++i) {
            int s = src[i], d = dst[i];
            atomicAdd(&g_degout[s], 1);
            int p = atomicAdd(&g_cnt[d], 1);
            if (p < CAP) g_ebuf[d * CAP + p] = s;
            else { int k = atomicAdd(g_ovfn, 1); if (k < MAX_OVF) g_ovf[k] = make_int2(d, s); }
        }
    }
}

// Tiny: srcnorm = rsqrt(max(degout,1)).
__global__ void k_norm(int n) {
    int i = blockIdx.x * blockDim.x + threadIdx.x;
    if (i < n) g_srcnorm[i] = rsqrtf(fmaxf((float)g_degout[i], 1.f));
}

// Fused gather-SpMM + epilogue. TWO nodes per warp (one per 16-lane half,
// float4 per lane). Main loop covers only FULL groups of 4 valid edges:
// zero predication, 32-bit index math, branch-free body, unroll 4 (median
// node = exactly 4 groups). One peeled tail handles 0-3 leftover edges.
// 128-thread blocks: finer block-retirement granularity vs degree imbalance.
__global__ void __launch_bounds__(128, 12)
k_gather(const float* __restrict__ feat,
         const float* __restrict__ hw,
         const float* __restrict__ hb,
         const int* __restrict__ niter_p,
         float* __restrict__ out, int n) {
    int gwarp = (blockIdx.x * blockDim.x + threadIdx.x) >> 5;
    int lane  = threadIdx.x & 31;
    int half  = lane >> 4;
    int hl    = lane & 15;
    int node  = gwarp * 2 + half;
    bool active = node < n;
    int nodec = active ? node : 0;
    unsigned hmask = half ? 0xFFFF0000u : 0x0000FFFFu;

    int deg  = active ? g_cnt[nodec] : 0;   // true in-degree
    int degb = min(deg, CAP);
    int full = degb & ~3;                   // edges in complete groups
    int rem  = degb - full;                 // 0..3 leftover edges
    float dn = rsqrtf(fmaxf((float)deg, 1.f));

    const int*    bin = g_ebuf + nodec * CAP;
    const float4* F4  = (const float4*)feat;
    float4 a0 = make_float4(0.f, 0.f, 0.f, 0.f);
    float4 a1 = make_float4(0.f, 0.f, 0.f, 0.f);

    #pragma unroll 4
    for (int k = 0; k < full; k += 4) {
        int4 s4 = *(const int4*)(bin + k);   // uniform within the half
        float n0 = g_srcnorm[s4.x];          // uniform broadcast loads
        float n1 = g_srcnorm[s4.y];
        float n2 = g_srcnorm[s4.z];
        float n3 = g_srcnorm[s4.w];
        float4 v0 = F4[(s4.x << 4) + hl];    // 32-bit index math
        float4 v1 = F4[(s4.y << 4) + hl];
        float4 v2 = F4[(s4.z << 4) + hl];
        float4 v3 = F4[(s4.w << 4) + hl];
        a0.x += n0 * v0.x; a0.y += n0 * v0.y; a0.z += n0 * v0.z; a0.w += n0 * v0.w;
        a1.x += n1 * v1.x; a1.y += n1 * v1.y; a1.z += n1 * v1.z; a1.w += n1 * v1.w;
        a0.x += n2 * v2.x; a0.y += n2 * v2.y; a0.z += n2 * v2.z; a0.w += n2 * v2.w;
        a1.x += n3 * v3.x; a1.y += n3 * v3.y; a1.z += n3 * v3.z; a1.w += n3 * v3.w;
    }
    if (rem) {                               // peeled tail (bin+full+3 < CAP)
        int4 s4 = *(const int4*)(bin + full);
        float n0 = g_srcnorm[s4.x];          // rem >= 1 always valid
        float n1 = (rem > 1) ? g_srcnorm[s4.y] : 0.f;
        float n2 = (rem > 2) ? g_srcnorm[s4.z] : 0.f;
        int sy = (rem > 1) ? s4.y : 0;       // keep feature reads in-bounds
        int sz = (rem > 2) ? s4.z : 0;
        float4 v0 = F4[(s4.x << 4) + hl];
        float4 v1 = F4[(sy << 4) + hl];
        float4 v2 = F4[(sz << 4) + hl];
        a0.x += n0 * v0.x; a0.y += n0 * v0.y; a0.z += n0 * v0.z; a0.w += n0 * v0.w;
        a1.x += n1 * v1.x; a1.y += n1 * v1.y; a1.z += n1 * v1.z; a1.w += n1 * v1.w;
        a0.x += n2 * v2.x; a0.y += n2 * v2.y; a0.z += n2 * v2.z; a0.w += n2 * v2.w;
    }
    float4 acc;
    acc.x = a0.x + a1.x; acc.y = a0.y + a1.y;
    acc.z = a0.z + a1.z; acc.w = a0.w + a1.w;

    // Overflow edges (empty in practice; correct if not).
    if (deg > CAP) {
        int novf = min(*g_ovfn, MAX_OVF);
        for (int i = 0; i < novf; i++) {
            int2 pr = g_ovf[i];
            if (pr.x == node) {
                float sn = g_srcnorm[pr.y];
                float4 v = F4[(pr.y << 4) + hl];
                acc.x += sn * v.x; acc.y += sn * v.y;
                acc.z += sn * v.z; acc.w += sn * v.w;
            }
        }
    }

    // prop = acc * dn; halting head
    float4 p;
    p.x = acc.x * dn; p.y = acc.y * dn; p.z = acc.z * dn; p.w = acc.w * dn;
    float4 w = ((const float4*)hw)[hl];
    float dot = w.x * p.x + w.y * p.y + w.z * p.z + w.w * p.w;
    #pragma unroll
    for (int o = 8; o > 0; o >>= 1)
        dot += __shfl_xor_sync(hmask, dot, o, 16);
    float z = dot + hb[0];
    float h = __fdividef(1.f, 1.f + __expf(-z));

    int niter = niter_p ? *niter_p : 10;
    float niter_f = (float)niter;

    // Closed-form halting recurrence (prob_t true for a consecutive prefix;
    // sum_h accumulated with the same fp additions in the same order).
    float sum_h = 0.f;
    int j = 0;
    while (j < niter && sum_h + h < 0.99f) { sum_h += h; ++j; }
    float steps = (float)(1 + j);
    bool prob0 = (h < 0.99f);
    float s0 = prob0 ? 2.f : 1.f;           // steps after t=0
    float sh0 = prob0 ? h : 0.f;            // sum_h after t=0
    bool cond0 = prob0 && (s0 < niter_f);
    float pfirst = cond0 ? sh0 : (1.f - sh0);
    int U = min(j + 1, niter);

    float cprop = pfirst + (float)(U - 1);
    float cfeat = 1.f - pfirst;

    if (active) {
        float4 f = F4[(node << 4) + hl];
        float inv_steps = __fdividef(1.f, steps);
        float4 r;
        r.x = (p.x * cprop + f.x * cfeat) * inv_steps;
        r.y = (p.y * cprop + f.y * cfeat) * inv_steps;
        r.z = (p.z * cprop + f.z * cfeat) * inv_steps;
        r.w = (p.w * cprop + f.w * cfeat) * inv_steps;
        ((float4*)out)[(node << 4) + hl] = r;
        if (hl == 0) {
            out[(size_t)n * H + node] = steps;            // steps
            out[(size_t)n * H + n + node] = 1.f - sum_h;  // remainder
        }
    }
}

extern "C" void kernel_launch(void* const* d_in, const int* in_sizes, int n_in,
                              void* d_out, int out_size) {
    const float* feat = (const float*)d_in[0];
    const int*   src  = (const int*)d_in[1];
    const int*   dst  = (const int*)d_in[2];
    const float* hw   = (const float*)d_in[3];
    const float* hb   = (const float*)d_in[4];
    const int*   nit  = (n_in >= 6) ? (const int*)d_in[5] : nullptr;

    int n = in_sizes[0] / H;
    int e = in_sizes[1];
    float* out = (float*)d_out;

    k_zero<<<(META_INTS / 4 + 255) / 256, 256>>>();
    k_bin<<<((e + 7) / 8 + 255) / 256, 256>>>(src, dst, e);
    k_norm<<<(n + 255) / 256, 256>>>(n);
    {
        long long threads = (long long)((n + 1) / 2) * 32;
        int blocks = (int)((threads + 127) / 128);
        k_gather<<<blocks, 128>>>(feat, hw, hb, nit, out, n);
    }
}

// round 17
// speedup vs baseline: 1.0441x; 1.0441x over previous
#include <cuda_runtime.h>
#include <math.h>

#define H 64
#define MAX_N 65536
#define CAP 64
#define MAX_OVF 65536

// Fused counter block: [0, MAX_N) = in-degree bin cursors (cnt),
// [MAX_N, 2*MAX_N) = out-degree, [2*MAX_N] = overflow counter (padded to 4).
#define META_INTS (2 * MAX_N + 4)
__device__ int   g_meta[META_INTS];
__device__ float g_srcnorm[MAX_N];      // rsqrt(max(degout,1))
__device__ int   g_ebuf[MAX_N * CAP];   // dst-binned src indices
__device__ int2  g_ovf[MAX_OVF];        // overflow (dst, src) pairs

#define g_cnt    (g_meta)
#define g_degout (g_meta + MAX_N)
#define g_ovfn   (g_meta + 2 * MAX_N)

// Zero + L2-warm all counters. int4 stores, one pass.
__global__ void k_zero() {
    int i = blockIdx.x * blockDim.x + threadIdx.x;
    if (i < META_INTS / 4)
        ((int4*)g_meta)[i] = make_int4(0, 0, 0, 0);
}

// One pass over edges: out-degree histogram + dst-binning. 2 edges/thread:
// 400K threads resident -> maximum chip-wide outstanding atomics
// (the kernel is atomic-latency-bound, not per-thread-MLP-bound).
__global__ void k_bin(const int* __restrict__ src, const int* __restrict__ dst, int e) {
    int t = blockIdx.x * blockDim.x + threadIdx.x;
    int i = t * 2;
    if (i + 1 < e) {
        int2 s2 = *(const int2*)(src + i);
        int2 d2 = *(const int2*)(dst + i);
        atomicAdd(&g_degout[s2.x], 1);
        atomicAdd(&g_degout[s2.y], 1);
        int p0 = atomicAdd(&g_cnt[d2.x], 1);
        int p1 = atomicAdd(&g_cnt[d2.y], 1);
        if (p0 < CAP) g_ebuf[d2.x * CAP + p0] = s2.x;
        else { int k = atomicAdd(g_ovfn, 1); if (k < MAX_OVF) g_ovf[k] = make_int2(d2.x, s2.x); }
        if (p1 < CAP) g_ebuf[d2.y * CAP + p1] = s2.y;
        else { int k = atomicAdd(g_ovfn, 1); if (k < MAX_OVF) g_ovf[k] = make_int2(d2.y, s2.y); }
    } else if (i < e) {
        int s = src[i], d = dst[i];
        atomicAdd(&g_degout[s], 1);
        int p = atomicAdd(&g_cnt[d], 1);
        if (p < CAP) g_ebuf[d * CAP + p] = s;
        else { int k = atomicAdd(g_ovfn, 1); if (k < MAX_OVF) g_ovf[k] = make_int2(d, s); }
    }
}

// Tiny: srcnorm = rsqrt(max(degout,1)).
__global__ void k_norm(int n) {
    int i = blockIdx.x * blockDim.x + threadIdx.x;
    if (i < n) g_srcnorm[i] = rsqrtf(fmaxf((float)g_degout[i], 1.f));
}

// Fused gather-SpMM + epilogue (R15 configuration — measured best 28.1us).
// TWO nodes per warp (one per 16-lane half, float4 per lane). Main loop
// covers only FULL groups of 4 valid edges: zero predication, 32-bit index
// math, branch-free body. One peeled tail handles 0-3 leftover edges.
__global__ void __launch_bounds__(256, 6)
k_gather(const float* __restrict__ feat,
         const float* __restrict__ hw,
         const float* __restrict__ hb,
         const int* __restrict__ niter_p,
         float* __restrict__ out, int n) {
    int gwarp = (blockIdx.x * blockDim.x + threadIdx.x) >> 5;
    int lane  = threadIdx.x & 31;
    int half  = lane >> 4;
    int hl    = lane & 15;
    int node  = gwarp * 2 + half;
    bool active = node < n;
    int nodec = active ? node : 0;
    unsigned hmask = half ? 0xFFFF0000u : 0x0000FFFFu;

    int deg  = active ? g_cnt[nodec] : 0;   // true in-degree
    int degb = min(deg, CAP);
    int full = degb & ~3;                   // edges in complete groups
    int rem  = degb - full;                 // 0..3 leftover edges
    float dn = rsqrtf(fmaxf((float)deg, 1.f));

    const int*    bin = g_ebuf + nodec * CAP;
    const float4* F4  = (const float4*)feat;
    float4 a0 = make_float4(0.f, 0.f, 0.f, 0.f);
    float4 a1 = make_float4(0.f, 0.f, 0.f, 0.f);

    #pragma unroll 2
    for (int k = 0; k < full; k += 4) {
        int4 s4 = *(const int4*)(bin + k);   // uniform within the half
        float n0 = g_srcnorm[s4.x];          // uniform broadcast loads
        float n1 = g_srcnorm[s4.y];
        float n2 = g_srcnorm[s4.z];
        float n3 = g_srcnorm[s4.w];
        float4 v0 = F4[(s4.x << 4) + hl];    // 32-bit index math
        float4 v1 = F4[(s4.y << 4) + hl];
        float4 v2 = F4[(s4.z << 4) + hl];
        float4 v3 = F4[(s4.w << 4) + hl];
        a0.x += n0 * v0.x; a0.y += n0 * v0.y; a0.z += n0 * v0.z; a0.w += n0 * v0.w;
        a1.x += n1 * v1.x; a1.y += n1 * v1.y; a1.z += n1 * v1.z; a1.w += n1 * v1.w;
        a0.x += n2 * v2.x; a0.y += n2 * v2.y; a0.z += n2 * v2.z; a0.w += n2 * v2.w;
        a1.x += n3 * v3.x; a1.y += n3 * v3.y; a1.z += n3 * v3.z; a1.w += n3 * v3.w;
    }
    if (rem) {                               // peeled tail (bin+full+3 < CAP)
        int4 s4 = *(const int4*)(bin + full);
        float n0 = g_srcnorm[s4.x];          // rem >= 1 always valid
        float n1 = (rem > 1) ? g_srcnorm[s4.y] : 0.f;
        float n2 = (rem > 2) ? g_srcnorm[s4.z] : 0.f;
        int sy = (rem > 1) ? s4.y : 0;       // keep feature reads in-bounds
        int sz = (rem > 2) ? s4.z : 0;
        float4 v0 = F4[(s4.x << 4) + hl];
        float4 v1 = F4[(sy << 4) + hl];
        float4 v2 = F4[(sz << 4) + hl];
        a0.x += n0 * v0.x; a0.y += n0 * v0.y; a0.z += n0 * v0.z; a0.w += n0 * v0.w;
        a1.x += n1 * v1.x; a1.y += n1 * v1.y; a1.z += n1 * v1.z; a1.w += n1 * v1.w;
        a0.x += n2 * v2.x; a0.y += n2 * v2.y; a0.z += n2 * v2.z; a0.w += n2 * v2.w;
    }
    float4 acc;
    acc.x = a0.x + a1.x; acc.y = a0.y + a1.y;
    acc.z = a0.z + a1.z; acc.w = a0.w + a1.w;

    // Overflow edges (empty in practice; correct if not).
    if (deg > CAP) {
        int novf = min(*g_ovfn, MAX_OVF);
        for (int i = 0; i < novf; i++) {
            int2 pr = g_ovf[i];
            if (pr.x == node) {
                float sn = g_srcnorm[pr.y];
                float4 v = F4[(pr.y << 4) + hl];
                acc.x += sn * v.x; acc.y += sn * v.y;
                acc.z += sn * v.z; acc.w += sn * v.w;
            }
        }
    }

    // prop = acc * dn; halting head
    float4 p;
    p.x = acc.x * dn; p.y = acc.y * dn; p.z = acc.z * dn; p.w = acc.w * dn;
    float4 w = ((const float4*)hw)[hl];
    float dot = w.x * p.x + w.y * p.y + w.z * p.z + w.w * p.w;
    #pragma unroll
    for (int o = 8; o > 0; o >>= 1)
        dot += __shfl_xor_sync(hmask, dot, o, 16);
    float z = dot + hb[0];
    float h = __fdividef(1.f, 1.f + __expf(-z));

    int niter = niter_p ? *niter_p : 10;
    float niter_f = (float)niter;

    // Closed-form halting recurrence (prob_t true for a consecutive prefix;
    // sum_h accumulated with the same fp additions in the same order).
    float sum_h = 0.f;
    int j = 0;
    while (j < niter && sum_h + h < 0.99f) { sum_h += h; ++j; }
    float steps = (float)(1 + j);
    bool prob0 = (h < 0.99f);
    float s0 = prob0 ? 2.f : 1.f;           // steps after t=0
    float sh0 = prob0 ? h : 0.f;            // sum_h after t=0
    bool cond0 = prob0 && (s0 < niter_f);
    float pfirst = cond0 ? sh0 : (1.f - sh0);
    int U = min(j + 1, niter);

    float cprop = pfirst + (float)(U - 1);
    float cfeat = 1.f - pfirst;

    if (active) {
        float4 f = F4[(node << 4) + hl];
        float inv_steps = __fdividef(1.f, steps);
        float4 r;
        r.x = (p.x * cprop + f.x * cfeat) * inv_steps;
        r.y = (p.y * cprop + f.y * cfeat) * inv_steps;
        r.z = (p.z * cprop + f.z * cfeat) * inv_steps;
        r.w = (p.w * cprop + f.w * cfeat) * inv_steps;
        ((float4*)out)[(node << 4) + hl] = r;
        if (hl == 0) {
            out[(size_t)n * H + node] = steps;            // steps
            out[(size_t)n * H + n + node] = 1.f - sum_h;  // remainder
        }
    }
}

extern "C" void kernel_launch(void* const* d_in, const int* in_sizes, int n_in,
                              void* d_out, int out_size) {
    const float* feat = (const float*)d_in[0];
    const int*   src  = (const int*)d_in[1];
    const int*   dst  = (const int*)d_in[2];
    const float* hw   = (const float*)d_in[3];
    const float* hb   = (const float*)d_in[4];
    const int*   nit  = (n_in >= 6) ? (const int*)d_in[5] : nullptr;

    int n = in_sizes[0] / H;
    int e = in_sizes[1];
    float* out = (float*)d_out;

    k_zero<<<(META_INTS / 4 + 255) / 256, 256>>>();
    k_bin<<<((e + 1) / 2 + 255) / 256, 256>>>(src, dst, e);
    k_norm<<<(n + 255) / 256, 256>>>(n);
    {
        long long threads = (long long)((n + 1) / 2) * 32;
        int blocks = (int)((threads + 255) / 256);
        k_gather<<<blocks, 256>>>(feat, hw, hb, nit, out, n);
    }
}